// round 1
// baseline (speedup 1.0000x reference)
#include <cuda_runtime.h>
#include <math.h>

#define Bb 16
#define Nn 8192
#define Dd 384
#define KN 16
#define KD 8
#define Hh 128
#define STEPS 3
#define M_TOT (Bb*Nn)   // 131072

// ---- scratch (alloc-free: __device__ globals, fully rewritten every launch) ----
__device__ float g_Cc[(size_t)M_TOT*Hh];      // coin hidden pre-act (sent part)   64MB
__device__ float g_Cp[(size_t)M_TOT*Hh];      // path hidden pre-act (sent part)   64MB
__device__ float g_amps[M_TOT*KD];            // coin amplitudes                    4MB
__device__ float g_ns[STEPS*M_TOT*KD];        // raw walk states per step          12MB
__device__ float g_qh[2*Bb*Hh];               // per-batch q@W + bias (coin, path)
__device__ float g_part[Bb*(Nn/32)];          // per-block sumsq partials
__device__ float g_inv[STEPS*Bb];             // 1/||ns|| per step per batch

// ---------------------------------------------------------------------------
// per-batch q contribution: qh[which][b][h] = bias[h] + sum_k q[b,k]*W1[rowoff+k][h]
// which=0: coin (rows 384..767), which=1: path (rows 392..775)
// ---------------------------------------------------------------------------
__global__ void qh_kernel(const float* __restrict__ q,
                          const float* __restrict__ cw1, const float* __restrict__ cb1,
                          const float* __restrict__ pw1, const float* __restrict__ pb1) {
    int b = blockIdx.x, which = blockIdx.y, h = threadIdx.x;
    const float* w1   = which ? pw1 : cw1;
    const float* bias = which ? pb1 : cb1;
    int rowoff = which ? (Dd + KD) : Dd;
    const float* qb = q + b*Dd;
    float acc = bias[h];
    #pragma unroll 4
    for (int k = 0; k < Dd; k++)
        acc = fmaf(qb[k], w1[(size_t)(rowoff + k)*Hh + h], acc);
    g_qh[(which*Bb + b)*Hh + h] = acc;
}

// ---------------------------------------------------------------------------
// Main GEMM: C[y] = sent[131072,384] @ W_y[0:384, 0:128]
//   blockIdx.y = 0 -> coin_w1 -> g_Cc ; 1 -> path_w1 -> g_Cp
// 128x128 block tile, 8x8 per thread, K-chunks of 8.
// ---------------------------------------------------------------------------
__global__ void __launch_bounds__(256, 2)
gemm_kernel(const float* __restrict__ A,
            const float* __restrict__ cw1, const float* __restrict__ pw1) {
    const float* W = blockIdx.y ? pw1 : cw1;
    float* C       = blockIdx.y ? g_Cp : g_Cc;

    __shared__ float As[8][128];   // transposed A chunk
    __shared__ float Bs[8][128];

    int tid = threadIdx.x;
    int tx = tid & 15, ty = tid >> 4;
    int ar = tid >> 1, akq = (tid & 1) * 4;      // A-load: row, k-quad
    int bkr = tid >> 5, bc = (tid & 31) * 4;     // B-load: k-row, col
    size_t row0 = (size_t)blockIdx.x * 128;

    const float* Ap = A + (row0 + ar)*Dd + akq;

    float acc[8][8];
    #pragma unroll
    for (int i = 0; i < 8; i++)
        #pragma unroll
        for (int j = 0; j < 8; j++) acc[i][j] = 0.f;

    for (int kc = 0; kc < Dd; kc += 8) {
        float4 av = *(const float4*)(Ap + kc);
        float4 bv = *(const float4*)(W + (size_t)(kc + bkr)*Hh + bc);
        As[akq+0][ar] = av.x; As[akq+1][ar] = av.y;
        As[akq+2][ar] = av.z; As[akq+3][ar] = av.w;
        *(float4*)&Bs[bkr][bc] = bv;
        __syncthreads();
        #pragma unroll
        for (int k = 0; k < 8; k++) {
            float a[8], bb[8];
            *(float4*)&a[0]  = *(const float4*)&As[k][ty*4];
            *(float4*)&a[4]  = *(const float4*)&As[k][64 + ty*4];
            *(float4*)&bb[0] = *(const float4*)&Bs[k][tx*4];
            *(float4*)&bb[4] = *(const float4*)&Bs[k][64 + tx*4];
            #pragma unroll
            for (int i = 0; i < 8; i++)
                #pragma unroll
                for (int j = 0; j < 8; j++)
                    acc[i][j] = fmaf(a[i], bb[j], acc[i][j]);
        }
        __syncthreads();
    }

    #pragma unroll
    for (int i = 0; i < 8; i++) {
        int r = (i < 4) ? (ty*4 + i) : (64 + ty*4 + (i - 4));
        float* Crow = C + (row0 + r)*Hh;
        *(float4*)&Crow[tx*4]      = make_float4(acc[i][0], acc[i][1], acc[i][2], acc[i][3]);
        *(float4*)&Crow[64 + tx*4] = make_float4(acc[i][4], acc[i][5], acc[i][6], acc[i][7]);
    }
}

// ---------------------------------------------------------------------------
// amps[r, :8] = relu(Cc[r,:] + qh_coin[b,:]) @ coin_w2 + coin_b2
// one warp per row (8 rows / 256-thread block)
// ---------------------------------------------------------------------------
__global__ void amps_kernel(const float* __restrict__ w2, const float* __restrict__ b2) {
    __shared__ float w2s[Hh*KD];
    int tid = threadIdx.x;
    for (int i = tid; i < Hh*KD; i += 256) w2s[i] = w2[i];
    __syncthreads();

    int r = blockIdx.x*8 + (tid >> 5);
    int l = tid & 31;
    int b = r >> 13;

    float4 c  = *(const float4*)&g_Cc[(size_t)r*Hh + l*4];
    float4 qv = *(const float4*)&g_qh[b*Hh + l*4];
    float hv[4] = { fmaxf(c.x+qv.x, 0.f), fmaxf(c.y+qv.y, 0.f),
                    fmaxf(c.z+qv.z, 0.f), fmaxf(c.w+qv.w, 0.f) };
    float acc[KD];
    #pragma unroll
    for (int j = 0; j < KD; j++) acc[j] = 0.f;
    #pragma unroll
    for (int i = 0; i < 4; i++)
        #pragma unroll
        for (int j = 0; j < KD; j++)
            acc[j] = fmaf(hv[i], w2s[(l*4 + i)*KD + j], acc[j]);
    #pragma unroll
    for (int m = 16; m > 0; m >>= 1)
        #pragma unroll
        for (int j = 0; j < KD; j++)
            acc[j] += __shfl_xor_sync(0xffffffffu, acc[j], m);
    if (l < KD) g_amps[r*KD + l] = acc[l] + b2[l];
}

// ---------------------------------------------------------------------------
// One walk step. coef = 1/sqrt(N*K) for step 0, else inv-norm of previous step.
// ns[step][b,n,k] = c(n) + sum_{valid nbr} c(nbr),  c(x) = coef*prev(x)*amps(x)
// Deterministic sumsq: block tree-reduce -> g_part (no atomics).
// ---------------------------------------------------------------------------
__global__ void walk_kernel(const int* __restrict__ nbrs, int step) {
    __shared__ int   nb[32*KN];
    __shared__ float red[256];
    int b  = blockIdx.y;
    int n0 = blockIdx.x * 32;
    int tid = threadIdx.x;

    const int* nb_g = nbrs + ((size_t)(b*Nn + n0))*KN;
    nb[tid]       = nb_g[tid];
    nb[tid + 256] = nb_g[tid + 256];
    __syncthreads();

    int node = tid >> 3, k = tid & 7;
    int n = n0 + node;
    float coef = (step == 0) ? 0.00390625f : g_inv[(step-1)*Bb + b];
    const float* amps_b = g_amps + (size_t)b*Nn*KD;
    const float* prev = g_ns;
    if (step > 0) prev = g_ns + (size_t)(step-1)*M_TOT*KD + (size_t)b*Nn*KD;

    float acc;
    if (step == 0) acc = amps_b[n*KD + k] * coef;
    else           acc = prev[n*KD + k] * amps_b[n*KD + k] * coef;

    #pragma unroll
    for (int j = 0; j < KN; j++) {
        int idx = nb[node*KN + j];
        if (idx >= 0 && idx < Nn) {
            float v = amps_b[idx*KD + k] * coef;
            if (step > 0) v *= prev[idx*KD + k];
            acc += v;
        }
    }
    g_ns[(size_t)step*M_TOT*KD + ((size_t)b*Nn + n)*KD + k] = acc;

    red[tid] = acc * acc;
    __syncthreads();
    for (int s = 128; s > 0; s >>= 1) {
        if (tid < s) red[tid] += red[tid + s];
        __syncthreads();
    }
    if (tid == 0) g_part[b*(Nn/32) + blockIdx.x] = red[0];
}

__global__ void reduce_kernel(int step) {
    __shared__ float red[256];
    int b = blockIdx.x, tid = threadIdx.x;
    red[tid] = g_part[b*(Nn/32) + tid];
    __syncthreads();
    for (int s = 128; s > 0; s >>= 1) {
        if (tid < s) red[tid] += red[tid + s];
        __syncthreads();
    }
    if (tid == 0) {
        float ss = red[0];
        g_inv[step*Bb + b] = (ss > 0.f) ? (1.0f / sqrtf(ss)) : 1.0f;
    }
}

// ---------------------------------------------------------------------------
// Final path MLP:
// h = relu(Cp[r,:] + qh_path[b,:] + state[r,:8] @ W1[384:392, :])
// out[r] = h @ path_w2 + path_b2,  state = ns[2] * inv[2]
// one warp per row
// ---------------------------------------------------------------------------
__global__ void final_kernel(const float* __restrict__ pw1,
                             const float* __restrict__ w2, const float* __restrict__ b2,
                             float* __restrict__ out) {
    __shared__ float wst[KD*Hh];
    __shared__ float w2s[Hh];
    int tid = threadIdx.x;
    for (int i = tid; i < KD*Hh; i += 256) wst[i] = pw1[(size_t)Dd*Hh + i];
    if (tid < Hh) w2s[tid] = w2[tid];
    __syncthreads();

    int r = blockIdx.x*8 + (tid >> 5);
    int l = tid & 31;
    int b = r >> 13;

    float inv = g_inv[(STEPS-1)*Bb + b];
    const float* nsf = g_ns + (size_t)(STEPS-1)*M_TOT*KD + (size_t)r*KD;
    float s[KD];
    #pragma unroll
    for (int k = 0; k < KD; k++) s[k] = nsf[k] * inv;

    float4 c  = *(const float4*)&g_Cp[(size_t)r*Hh + l*4];
    float4 qv = *(const float4*)&g_qh[(Bb + b)*Hh + l*4];
    float hv[4] = { c.x+qv.x, c.y+qv.y, c.z+qv.z, c.w+qv.w };
    #pragma unroll
    for (int k = 0; k < KD; k++)
        #pragma unroll
        for (int i = 0; i < 4; i++)
            hv[i] = fmaf(s[k], wst[k*Hh + l*4 + i], hv[i]);

    float part = 0.f;
    #pragma unroll
    for (int i = 0; i < 4; i++) {
        float h = fmaxf(hv[i], 0.f);
        part = fmaf(h, w2s[l*4 + i], part);
    }
    #pragma unroll
    for (int m = 16; m > 0; m >>= 1)
        part += __shfl_xor_sync(0xffffffffu, part, m);
    if (l == 0) out[r] = part + b2[0];
}

// ---------------------------------------------------------------------------
extern "C" void kernel_launch(void* const* d_in, const int* in_sizes, int n_in,
                              void* d_out, int out_size) {
    const float* sent = (const float*)d_in[0];
    const float* q    = (const float*)d_in[1];
    const int*   nbrs = (const int*)  d_in[2];
    const float* cw1  = (const float*)d_in[3];
    const float* cb1  = (const float*)d_in[4];
    const float* cw2  = (const float*)d_in[5];
    const float* cb2  = (const float*)d_in[6];
    const float* pw1  = (const float*)d_in[7];
    const float* pb1  = (const float*)d_in[8];
    const float* pw2  = (const float*)d_in[9];
    const float* pb2  = (const float*)d_in[10];
    float* out = (float*)d_out;

    qh_kernel<<<dim3(Bb, 2), Hh>>>(q, cw1, cb1, pw1, pb1);
    gemm_kernel<<<dim3(M_TOT/128, 2), 256>>>(sent, cw1, pw1);
    amps_kernel<<<M_TOT/8, 256>>>(cw2, cb2);
    for (int s = 0; s < STEPS; s++) {
        walk_kernel<<<dim3(Nn/32, Bb), 256>>>(nbrs, s);
        reduce_kernel<<<Bb, 256>>>(s);
    }
    final_kernel<<<M_TOT/8, 256>>>(pw1, pw2, pb2, out);
}

// round 2
// speedup vs baseline: 1.8232x; 1.8232x over previous
#include <cuda_runtime.h>
#include <cuda_bf16.h>
#include <math.h>

#define Bb 16
#define Nn 8192
#define Dd 384
#define KN 16
#define KD 8
#define Hh 128
#define STEPS 3
#define M_TOT (Bb*Nn)   // 131072

#define APAD 24    // halves per A smem row (48B stride: conflict-free ldmatrix)
#define BPAD 136   // halves per B smem row (272B stride: conflict-free ldmatrix.trans)

// ---- scratch (alloc-free: __device__ globals, fully rewritten every launch) ----
__device__ float g_Cp[(size_t)M_TOT*Hh];      // path hidden pre-act (sent part)   64MB
__device__ float g_amps[M_TOT*KD];            // coin amplitudes                    4MB
__device__ float g_ns[STEPS*M_TOT*KD];        // raw walk states per step          12MB
__device__ float g_qh[2*Bb*Hh];               // per-batch q@W + bias (coin, path)
__device__ float g_part[Bb*(Nn/32)];          // per-block sumsq partials
__device__ float g_inv[STEPS*Bb];             // 1/||ns|| per step per batch

// ---------------------------------------------------------------------------
__device__ __forceinline__ void ldsm4(unsigned &r0, unsigned &r1, unsigned &r2, unsigned &r3,
                                      unsigned addr) {
    asm volatile("ldmatrix.sync.aligned.m8n8.x4.shared.b16 {%0,%1,%2,%3}, [%4];"
                 : "=r"(r0), "=r"(r1), "=r"(r2), "=r"(r3) : "r"(addr));
}
__device__ __forceinline__ void ldsm4t(unsigned &r0, unsigned &r1, unsigned &r2, unsigned &r3,
                                       unsigned addr) {
    asm volatile("ldmatrix.sync.aligned.m8n8.x4.trans.shared.b16 {%0,%1,%2,%3}, [%4];"
                 : "=r"(r0), "=r"(r1), "=r"(r2), "=r"(r3) : "r"(addr));
}
__device__ __forceinline__ void mma16816(float* c, const unsigned* a, unsigned b0, unsigned b1) {
    asm volatile(
        "mma.sync.aligned.m16n8k16.row.col.f32.bf16.bf16.f32 "
        "{%0,%1,%2,%3}, {%4,%5,%6,%7}, {%8,%9}, {%0,%1,%2,%3};"
        : "+f"(c[0]), "+f"(c[1]), "+f"(c[2]), "+f"(c[3])
        : "r"(a[0]), "r"(a[1]), "r"(a[2]), "r"(a[3]), "r"(b0), "r"(b1));
}

// ---------------------------------------------------------------------------
// per-batch q contribution: qh[which][b][h] = bias[h] + sum_k q[b,k]*W1[rowoff+k][h]
// ---------------------------------------------------------------------------
__global__ void qh_kernel(const float* __restrict__ q,
                          const float* __restrict__ cw1, const float* __restrict__ cb1,
                          const float* __restrict__ pw1, const float* __restrict__ pb1) {
    int b = blockIdx.x, which = blockIdx.y, h = threadIdx.x;
    const float* w1   = which ? pw1 : cw1;
    const float* bias = which ? pb1 : cb1;
    int rowoff = which ? (Dd + KD) : Dd;
    const float* qb = q + b*Dd;
    float acc = bias[h];
    #pragma unroll 4
    for (int k = 0; k < Dd; k++)
        acc = fmaf(qb[k], w1[(size_t)(rowoff + k)*Hh + h], acc);
    g_qh[(which*Bb + b)*Hh + h] = acc;
}

// ---------------------------------------------------------------------------
// Tensor-core GEMM: 128x128 tile of sent[131072,384] @ W[0:384,0:128]
// bf16 2-way split (hi/lo), 3 MMA passes: hi*hi + hi*lo + lo*hi. fp32 accum.
//   blockIdx.y = 0 -> coin_w1, fused coin layer-2 epilogue -> g_amps
//   blockIdx.y = 1 -> path_w1 -> g_Cp
// 8 warps: 4 (M) x 2 (N); warp tile 32x64; per-thread 2x8x4 fp32 accum.
// ---------------------------------------------------------------------------
__global__ void __launch_bounds__(256, 2)
gemm_mma(const float* __restrict__ A,
         const float* __restrict__ cw1, const float* __restrict__ pw1,
         const float* __restrict__ cw2, const float* __restrict__ cb2) {
    __shared__ __nv_bfloat16 a_sm[2][128*APAD];
    __shared__ __nv_bfloat16 b_sm[2][16*BPAD];
    __shared__ float ep_sm[32*130];           // coin epilogue staging
    __shared__ float w2s[Hh*KD + Hh + KD];    // coin w2 | qh | b2

    const int y = blockIdx.y;
    const float* W = y ? pw1 : cw1;
    const size_t row0 = (size_t)blockIdx.x * 128;
    const int tid = threadIdx.x;
    const int lane = tid & 31;
    const int wid  = tid >> 5;
    const int wm = wid >> 1, wn = wid & 1;

    float c[2][8][4];
    #pragma unroll
    for (int i = 0; i < 2; i++)
        #pragma unroll
        for (int j = 0; j < 8; j++)
            #pragma unroll
            for (int l = 0; l < 4; l++) c[i][j][l] = 0.f;

    // gmem-load assignments (2 float4 each for A and B per thread)
    const int ar0 = (tid*2)   >> 2, aq0 = ((tid*2)   & 3)*4;
    const int ar1 = (tid*2+1) >> 2, aq1 = ((tid*2+1) & 3)*4;
    const int bk0 = (tid*2)   >> 5, bc0 = ((tid*2)   & 31)*4;
    const int bk1 = (tid*2+1) >> 5, bc1 = ((tid*2+1) & 31)*4;
    const float* Abase = A + row0*Dd;

    float4 av0, av1, bv0, bv1;
    av0 = *(const float4*)(Abase + (size_t)ar0*Dd + aq0);
    av1 = *(const float4*)(Abase + (size_t)ar1*Dd + aq1);
    bv0 = *(const float4*)(W + (size_t)bk0*Hh + bc0);
    bv1 = *(const float4*)(W + (size_t)bk1*Hh + bc1);

    // ldmatrix base addresses
    const unsigned a_base0 = (unsigned)__cvta_generic_to_shared(a_sm[0]);
    const unsigned a_base1 = (unsigned)__cvta_generic_to_shared(a_sm[1]);
    const unsigned b_base0 = (unsigned)__cvta_generic_to_shared(b_sm[0]);
    const unsigned b_base1 = (unsigned)__cvta_generic_to_shared(b_sm[1]);
    const int a_row_off = ((lane & 15)*APAD + (lane >> 4)*8)*2;   // + rowgroup base
    const int b_k = (lane & 7) + ((lane >> 3) & 1)*8;
    const int b_off = (b_k*BPAD + wn*64 + (lane >> 4)*8)*2;       // + pair*16*2

    for (int it = 0; it < 24; it++) {
        // ---- convert + store current chunk ----
        {
            float va[8] = {av0.x, av0.y, av0.z, av0.w, av1.x, av1.y, av1.z, av1.w};
            int rr[2] = {ar0, ar1}, qq[2] = {aq0, aq1};
            #pragma unroll
            for (int i = 0; i < 2; i++) {
                #pragma unroll
                for (int j = 0; j < 4; j += 2) {
                    float x0 = va[i*4 + j], x1 = va[i*4 + j + 1];
                    __nv_bfloat16 h0 = __float2bfloat16(x0);
                    __nv_bfloat16 h1 = __float2bfloat16(x1);
                    __nv_bfloat16 l0 = __float2bfloat16(x0 - __bfloat162float(h0));
                    __nv_bfloat16 l1 = __float2bfloat16(x1 - __bfloat162float(h1));
                    __nv_bfloat162 hp; hp.x = h0; hp.y = h1;
                    __nv_bfloat162 lp; lp.x = l0; lp.y = l1;
                    *(__nv_bfloat162*)&a_sm[0][rr[i]*APAD + qq[i] + j] = hp;
                    *(__nv_bfloat162*)&a_sm[1][rr[i]*APAD + qq[i] + j] = lp;
                }
            }
            float vb[8] = {bv0.x, bv0.y, bv0.z, bv0.w, bv1.x, bv1.y, bv1.z, bv1.w};
            int kk2[2] = {bk0, bk1}, cc[2] = {bc0, bc1};
            #pragma unroll
            for (int i = 0; i < 2; i++) {
                #pragma unroll
                for (int j = 0; j < 4; j += 2) {
                    float x0 = vb[i*4 + j], x1 = vb[i*4 + j + 1];
                    __nv_bfloat16 h0 = __float2bfloat16(x0);
                    __nv_bfloat16 h1 = __float2bfloat16(x1);
                    __nv_bfloat16 l0 = __float2bfloat16(x0 - __bfloat162float(h0));
                    __nv_bfloat16 l1 = __float2bfloat16(x1 - __bfloat162float(h1));
                    __nv_bfloat162 hp; hp.x = h0; hp.y = h1;
                    __nv_bfloat162 lp; lp.x = l0; lp.y = l1;
                    *(__nv_bfloat162*)&b_sm[0][kk2[i]*BPAD + cc[i] + j] = hp;
                    *(__nv_bfloat162*)&b_sm[1][kk2[i]*BPAD + cc[i] + j] = lp;
                }
            }
        }
        __syncthreads();

        // ---- prefetch next chunk (overlaps with MMA) ----
        if (it < 23) {
            int kc = (it + 1)*16;
            av0 = *(const float4*)(Abase + (size_t)ar0*Dd + kc + aq0);
            av1 = *(const float4*)(Abase + (size_t)ar1*Dd + kc + aq1);
            bv0 = *(const float4*)(W + (size_t)(kc + bk0)*Hh + bc0);
            bv1 = *(const float4*)(W + (size_t)(kc + bk1)*Hh + bc1);
        }

        // ---- MMA: 3 split passes ----
        #pragma unroll
        for (int p = 0; p < 3; p++) {
            const unsigned abase = (p == 2) ? a_base1 : a_base0;
            const unsigned bbase = (p == 1) ? b_base1 : b_base0;
            unsigned afr[2][4];
            #pragma unroll
            for (int rg = 0; rg < 2; rg++) {
                unsigned addr = abase + (unsigned)((wm*32 + rg*16)*APAD*2 + a_row_off);
                ldsm4(afr[rg][0], afr[rg][1], afr[rg][2], afr[rg][3], addr);
            }
            #pragma unroll
            for (int pr = 0; pr < 4; pr++) {
                unsigned b0, b1, b2_, b3;
                unsigned addr = bbase + (unsigned)(pr*32 + b_off);
                ldsm4t(b0, b1, b2_, b3, addr);
                #pragma unroll
                for (int rg = 0; rg < 2; rg++) {
                    mma16816(c[rg][2*pr],     afr[rg], b0,  b1);
                    mma16816(c[rg][2*pr + 1], afr[rg], b2_, b3);
                }
            }
        }
        __syncthreads();
    }

    // ---- epilogue ----
    const int gr = lane >> 2, gc2 = (lane & 3)*2;
    if (y == 1) {
        #pragma unroll
        for (int rg = 0; rg < 2; rg++)
            #pragma unroll
            for (int ng = 0; ng < 8; ng++) {
                int r = wm*32 + rg*16 + gr;
                int col = wn*64 + ng*8 + gc2;
                *(float2*)&g_Cp[(row0 + r)*Hh + col]     = make_float2(c[rg][ng][0], c[rg][ng][1]);
                *(float2*)&g_Cp[(row0 + r + 8)*Hh + col] = make_float2(c[rg][ng][2], c[rg][ng][3]);
            }
    } else {
        // fused coin layer-2: amps = relu(C + qh) @ w2 + b2
        int b = blockIdx.x >> 6;
        for (int i = tid; i < Hh*KD; i += 256) w2s[i] = cw2[i];
        if (tid < Hh) w2s[Hh*KD + tid] = g_qh[b*Hh + tid];
        if (tid < KD) w2s[Hh*KD + Hh + tid] = cb2[tid];
        __syncthreads();
        const float* qhs = &w2s[Hh*KD];
        const float* b2s = &w2s[Hh*KD + Hh];

        for (int rc = 0; rc < 4; rc++) {
            if (wm == rc) {
                #pragma unroll
                for (int rg = 0; rg < 2; rg++)
                    #pragma unroll
                    for (int ng = 0; ng < 8; ng++) {
                        int r = rg*16 + gr;
                        int col = wn*64 + ng*8 + gc2;
                        float2 lo = make_float2(fmaxf(c[rg][ng][0] + qhs[col],     0.f),
                                                fmaxf(c[rg][ng][1] + qhs[col + 1], 0.f));
                        float2 hi = make_float2(fmaxf(c[rg][ng][2] + qhs[col],     0.f),
                                                fmaxf(c[rg][ng][3] + qhs[col + 1], 0.f));
                        *(float2*)&ep_sm[r*130 + col]       = lo;
                        *(float2*)&ep_sm[(r + 8)*130 + col] = hi;
                    }
            }
            __syncthreads();
            int row = tid >> 3, kk = tid & 7;
            float acc = b2s[kk];
            #pragma unroll 8
            for (int h = 0; h < Hh; h++)
                acc = fmaf(ep_sm[row*130 + h], w2s[h*KD + kk], acc);
            g_amps[(row0 + rc*32 + row)*KD + kk] = acc;
            __syncthreads();
        }
    }
}

// ---------------------------------------------------------------------------
// One walk step. coef = 1/sqrt(N*K) for step 0, else inv-norm of previous step.
// ---------------------------------------------------------------------------
__global__ void walk_kernel(const int* __restrict__ nbrs, int step) {
    __shared__ int   nb[32*KN];
    __shared__ float red[256];
    int b  = blockIdx.y;
    int n0 = blockIdx.x * 32;
    int tid = threadIdx.x;

    const int* nb_g = nbrs + ((size_t)(b*Nn + n0))*KN;
    nb[tid]       = nb_g[tid];
    nb[tid + 256] = nb_g[tid + 256];
    __syncthreads();

    int node = tid >> 3, k = tid & 7;
    int n = n0 + node;
    float coef = (step == 0) ? 0.00390625f : g_inv[(step-1)*Bb + b];
    const float* amps_b = g_amps + (size_t)b*Nn*KD;
    const float* prev = g_ns;
    if (step > 0) prev = g_ns + (size_t)(step-1)*M_TOT*KD + (size_t)b*Nn*KD;

    float acc;
    if (step == 0) acc = amps_b[n*KD + k] * coef;
    else           acc = prev[n*KD + k] * amps_b[n*KD + k] * coef;

    #pragma unroll
    for (int j = 0; j < KN; j++) {
        int idx = nb[node*KN + j];
        if (idx >= 0 && idx < Nn) {
            float v = amps_b[idx*KD + k] * coef;
            if (step > 0) v *= prev[idx*KD + k];
            acc += v;
        }
    }
    g_ns[(size_t)step*M_TOT*KD + ((size_t)b*Nn + n)*KD + k] = acc;

    red[tid] = acc * acc;
    __syncthreads();
    for (int s = 128; s > 0; s >>= 1) {
        if (tid < s) red[tid] += red[tid + s];
        __syncthreads();
    }
    if (tid == 0) g_part[b*(Nn/32) + blockIdx.x] = red[0];
}

__global__ void reduce_kernel(int step) {
    __shared__ float red[256];
    int b = blockIdx.x, tid = threadIdx.x;
    red[tid] = g_part[b*(Nn/32) + tid];
    __syncthreads();
    for (int s = 128; s > 0; s >>= 1) {
        if (tid < s) red[tid] += red[tid + s];
        __syncthreads();
    }
    if (tid == 0) {
        float ss = red[0];
        g_inv[step*Bb + b] = (ss > 0.f) ? (1.0f / sqrtf(ss)) : 1.0f;
    }
}

// ---------------------------------------------------------------------------
// Final path MLP: h = relu(Cp + qh_path + state @ W1[384:392,:]); out = h@w2+b2
// ---------------------------------------------------------------------------
__global__ void final_kernel(const float* __restrict__ pw1,
                             const float* __restrict__ w2, const float* __restrict__ b2,
                             float* __restrict__ out) {
    __shared__ float wst[KD*Hh];
    __shared__ float w2s[Hh];
    int tid = threadIdx.x;
    for (int i = tid; i < KD*Hh; i += 256) wst[i] = pw1[(size_t)Dd*Hh + i];
    if (tid < Hh) w2s[tid] = w2[tid];
    __syncthreads();

    int r = blockIdx.x*8 + (tid >> 5);
    int l = tid & 31;
    int b = r >> 13;

    float inv = g_inv[(STEPS-1)*Bb + b];
    const float* nsf = g_ns + (size_t)(STEPS-1)*M_TOT*KD + (size_t)r*KD;
    float s[KD];
    #pragma unroll
    for (int k = 0; k < KD; k++) s[k] = nsf[k] * inv;

    float4 cc = *(const float4*)&g_Cp[(size_t)r*Hh + l*4];
    float4 qv = *(const float4*)&g_qh[(Bb + b)*Hh + l*4];
    float hv[4] = { cc.x+qv.x, cc.y+qv.y, cc.z+qv.z, cc.w+qv.w };
    #pragma unroll
    for (int k = 0; k < KD; k++)
        #pragma unroll
        for (int i = 0; i < 4; i++)
            hv[i] = fmaf(s[k], wst[k*Hh + l*4 + i], hv[i]);

    float part = 0.f;
    #pragma unroll
    for (int i = 0; i < 4; i++) {
        float h = fmaxf(hv[i], 0.f);
        part = fmaf(h, w2s[l*4 + i], part);
    }
    #pragma unroll
    for (int m = 16; m > 0; m >>= 1)
        part += __shfl_xor_sync(0xffffffffu, part, m);
    if (l == 0) out[r] = part + b2[0];
}

// ---------------------------------------------------------------------------
extern "C" void kernel_launch(void* const* d_in, const int* in_sizes, int n_in,
                              void* d_out, int out_size) {
    const float* sent = (const float*)d_in[0];
    const float* q    = (const float*)d_in[1];
    const int*   nbrs = (const int*)  d_in[2];
    const float* cw1  = (const float*)d_in[3];
    const float* cb1  = (const float*)d_in[4];
    const float* cw2  = (const float*)d_in[5];
    const float* cb2  = (const float*)d_in[6];
    const float* pw1  = (const float*)d_in[7];
    const float* pb1  = (const float*)d_in[8];
    const float* pw2  = (const float*)d_in[9];
    const float* pb2  = (const float*)d_in[10];
    float* out = (float*)d_out;

    qh_kernel<<<dim3(Bb, 2), Hh>>>(q, cw1, cb1, pw1, pb1);
    gemm_mma<<<dim3(M_TOT/128, 2), 256>>>(sent, cw1, pw1, cw2, cb2);
    for (int s = 0; s < STEPS; s++) {
        walk_kernel<<<dim3(Nn/32, Bb), 256>>>(nbrs, s);
        reduce_kernel<<<Bb, 256>>>(s);
    }
    final_kernel<<<M_TOT/8, 256>>>(pw1, pw2, pb2, out);
}

// round 4
// speedup vs baseline: 2.3776x; 1.3041x over previous
#include <cuda_runtime.h>
#include <cuda_fp16.h>
#include <math.h>
#include <stdint.h>

#define Bb 16
#define Nn 8192
#define Dd 384
#define KN 16
#define KD 8
#define Hh 128
#define STEPS 3
#define M_TOT (Bb*Nn)   // 131072
#define NB 256          // fused output width (coin 0..127 | path 128..255)

#define APAD 24         // halves per A smem row (48B stride, odd multiple of 16B)
#define BPAD 264        // halves per B smem row (528B stride, odd multiple of 16B)

// smem buffer layout (per double-buffer slot):
//   [0, 6144)      A hi  (128 x 16 fp16, APAD rows)
//   [6144, 12288)  A lo
//   [12288, 20736) B     (16 x 256 fp16, BPAD rows)
#define SMBUF 20736
#define SM_MAIN (2*SMBUF)          // 41472
// epilogue aliases: ep[128][132] @0 (67584B), w2s @67584, qh @71680, b2 @72192
#define EP_W2 67584
#define EP_QH 71680
#define EP_B2 72192
#define SM_TOTAL 73728

// ---- scratch (alloc-free: __device__ globals, fully rewritten every launch) ----
__device__ float g_Cp[(size_t)M_TOT*Hh];      // path hidden pre-act (sent part)   64MB
__device__ float g_amps[M_TOT*KD];            // coin amplitudes                    4MB
__device__ float g_ns[STEPS*M_TOT*KD];        // raw walk states per step          12MB
__device__ float g_qh[2*Bb*Hh];               // per-batch q@W + bias (coin, path)
__device__ float g_part[Bb*(Nn/32)];          // per-block sumsq partials
__device__ __half g_Bh[Dd*NB];                // fused W1, fp16, [kchunk][k16][n]

// ================= helpers =================
__device__ __forceinline__ uint32_t smem_u32(const void* p) {
    uint32_t a;
    asm("{ .reg .u64 t; cvta.to.shared.u64 t, %1; cvt.u32.u64 %0, t; }" : "=r"(a) : "l"(p));
    return a;
}
__device__ __forceinline__ void ldsm4(unsigned &r0, unsigned &r1, unsigned &r2, unsigned &r3,
                                      unsigned addr) {
    asm volatile("ldmatrix.sync.aligned.m8n8.x4.shared.b16 {%0,%1,%2,%3}, [%4];"
                 : "=r"(r0), "=r"(r1), "=r"(r2), "=r"(r3) : "r"(addr));
}
__device__ __forceinline__ void ldsm4t(unsigned &r0, unsigned &r1, unsigned &r2, unsigned &r3,
                                       unsigned addr) {
    asm volatile("ldmatrix.sync.aligned.m8n8.x4.trans.shared.b16 {%0,%1,%2,%3}, [%4];"
                 : "=r"(r0), "=r"(r1), "=r"(r2), "=r"(r3) : "r"(addr));
}
__device__ __forceinline__ void mma16816(float* c, const unsigned* a, unsigned b0, unsigned b1) {
    asm volatile(
        "mma.sync.aligned.m16n8k16.row.col.f32.f16.f16.f32 "
        "{%0,%1,%2,%3}, {%4,%5,%6,%7}, {%8,%9}, {%0,%1,%2,%3};"
        : "+f"(c[0]), "+f"(c[1]), "+f"(c[2]), "+f"(c[3])
        : "r"(a[0]), "r"(a[1]), "r"(a[2]), "r"(a[3]), "r"(b0), "r"(b1));
}
__device__ __forceinline__ uint32_t pack_h2(__half a, __half b) {
    __half2 t; t.x = a; t.y = b;
    return *(uint32_t*)&t;
}

// ---------------------------------------------------------------------------
// per-batch q contribution: qh[which][b][h] (fp32, exact path for q part)
// ---------------------------------------------------------------------------
__global__ void qh_kernel(const float* __restrict__ q,
                          const float* __restrict__ cw1, const float* __restrict__ cb1,
                          const float* __restrict__ pw1, const float* __restrict__ pb1) {
    int b = blockIdx.x, which = blockIdx.y, h = threadIdx.x;
    const float* w1   = which ? pw1 : cw1;
    const float* bias = which ? pb1 : cb1;
    int rowoff = which ? (Dd + KD) : Dd;
    const float* qb = q + b*Dd;
    float acc = bias[h];
    #pragma unroll 4
    for (int k = 0; k < Dd; k++)
        acc = fmaf(qb[k], w1[(size_t)(rowoff + k)*Hh + h], acc);
    g_qh[(which*Bb + b)*Hh + h] = acc;
}

// ---------------------------------------------------------------------------
// pre-convert fused W1 sent-block to fp16, layout [k/16][k%16][n] (n<128 coin)
// ---------------------------------------------------------------------------
__global__ void prepB_kernel(const float* __restrict__ cw1, const float* __restrict__ pw1) {
    int k = blockIdx.x;          // 0..383
    int n = threadIdx.x;         // 0..255
    const float* w = (n < Hh) ? cw1 : pw1;
    float v = w[(size_t)k*Hh + (n & (Hh-1))];
    g_Bh[(k >> 4)*(16*NB) + (k & 15)*NB + n] = __float2half_rn(v);
}

// ---------------------------------------------------------------------------
// HMMA GEMM: per CTA 128 rows x 256 cols, K=384 (24 chunks of 16).
// A split fp16 hi/lo (2 passes), B single fp16. fp32 accum.
// Fused epilogue: cols 0..127 -> coin layer-2 -> g_amps; cols 128..255 -> g_Cp.
// ---------------------------------------------------------------------------
__global__ void __launch_bounds__(512, 1)
gemm_hmma(const float* __restrict__ A,
          const float* __restrict__ cw2, const float* __restrict__ cb2) {
    extern __shared__ char smem[];
    const uint32_t sbase = smem_u32(smem);
    const int tid = threadIdx.x, lane = tid & 31, wid = tid >> 5;
    const int wm = wid >> 2, wn = wid & 3;
    const size_t row0 = (size_t)blockIdx.x * 128;

    float c[2][8][4];
    #pragma unroll
    for (int i = 0; i < 2; i++)
        #pragma unroll
        for (int j = 0; j < 8; j++)
            #pragma unroll
            for (int l = 0; l < 4; l++) c[i][j][l] = 0.f;

    // load assignments
    const int arow = tid >> 2, akq = (tid & 3)*4;      // A: 1 float4 / thread / chunk
    const float* Ap = A + (row0 + arow)*Dd + akq;
    const int bkk = tid >> 5, bnn = (tid & 31)*8;      // B: 1 uint4 / thread / chunk
    const uint32_t a_sts = (uint32_t)(arow*APAD + akq)*2;
    const uint32_t b_sts = 12288u + (uint32_t)(bkk*BPAD + bnn)*2;

    // ldmatrix lane offsets (proven R2 addressing)
    const uint32_t a_lane = (uint32_t)(((lane & 15)*APAD + (lane >> 4)*8)*2);
    const uint32_t b_lane = (uint32_t)(((((lane & 7) + ((lane >> 3) & 1)*8))*BPAD
                                        + wn*64 + (lane >> 4)*8)*2);

    float4 apre = *(const float4*)Ap;
    uint4  bpre = *(const uint4*)(g_Bh + tid*8);

    // ---- store chunk into buffer (A converted to hi/lo fp16) ----
    #define STS_CHUNK(bufbyte) do {                                            \
        char* _bc = smem + (bufbyte);                                          \
        float _v[4] = {apre.x, apre.y, apre.z, apre.w};                        \
        __half _h[4], _l[4];                                                   \
        _Pragma("unroll")                                                      \
        for (int _i = 0; _i < 4; _i++) {                                       \
            _h[_i] = __float2half_rn(_v[_i]);                                  \
            _l[_i] = __float2half_rn(_v[_i] - __half2float(_h[_i]));           \
        }                                                                      \
        *(uint2*)(_bc + a_sts) =                                               \
            make_uint2(pack_h2(_h[0], _h[1]), pack_h2(_h[2], _h[3]));          \
        *(uint2*)(_bc + 6144 + a_sts) =                                        \
            make_uint2(pack_h2(_l[0], _l[1]), pack_h2(_l[2], _l[3]));          \
        *(uint4*)(_bc + b_sts) = bpre;                                         \
    } while (0)

    STS_CHUNK(0);
    __syncthreads();

    for (int ch = 0; ch < 24; ch++) {
        const int cur = ch & 1;
        if (ch < 23) {
            apre = *(const float4*)(Ap + (ch + 1)*16);
            bpre = *(const uint4*)(g_Bh + (ch + 1)*4096 + tid*8);
        }
        // ---- MMA on buffer cur ----
        {
            const uint32_t sb0 = sbase + cur*SMBUF;
            unsigned bf[4][4];
            #pragma unroll
            for (int pr = 0; pr < 4; pr++)
                ldsm4t(bf[pr][0], bf[pr][1], bf[pr][2], bf[pr][3],
                       sb0 + 12288 + pr*32 + b_lane);
            #pragma unroll
            for (int p = 0; p < 2; p++) {
                const uint32_t ab = sb0 + (p ? 6144u : 0u);
                unsigned af[2][4];
                #pragma unroll
                for (int rg = 0; rg < 2; rg++)
                    ldsm4(af[rg][0], af[rg][1], af[rg][2], af[rg][3],
                          ab + (uint32_t)((wm*32 + rg*16)*48) + a_lane);
                #pragma unroll
                for (int pr = 0; pr < 4; pr++)
                    #pragma unroll
                    for (int rg = 0; rg < 2; rg++) {
                        mma16816(c[rg][2*pr],     af[rg], bf[pr][0], bf[pr][1]);
                        mma16816(c[rg][2*pr + 1], af[rg], bf[pr][2], bf[pr][3]);
                    }
            }
        }
        if (ch < 23) STS_CHUNK((cur ^ 1)*SMBUF);
        __syncthreads();
    }

    // ---- epilogue ----
    const int b = blockIdx.x >> 6;             // 64 tiles per batch
    float* ep   = (float*)smem;                // [128][132]
    float* w2s  = (float*)(smem + EP_W2);
    float* qhs  = (float*)(smem + EP_QH);
    float* b2s  = (float*)(smem + EP_B2);
    for (int i = tid; i < Hh*KD; i += 512) w2s[i] = cw2[i];
    if (tid < Hh) qhs[tid] = g_qh[b*Hh + tid];
    if (tid < KD) b2s[tid] = cb2[tid];
    __syncthreads();

    const int gr = lane >> 2, gc2 = (lane & 3)*2;
    if (wn < 2) {
        // coin half: stage relu(c + qh) into ep
        #pragma unroll
        for (int rg = 0; rg < 2; rg++)
            #pragma unroll
            for (int ng = 0; ng < 8; ng++) {
                int r = wm*32 + rg*16 + gr;
                int col = wn*64 + ng*8 + gc2;
                ep[r*132 + col]       = fmaxf(c[rg][ng][0] + qhs[col],     0.f);
                ep[r*132 + col + 1]   = fmaxf(c[rg][ng][1] + qhs[col + 1], 0.f);
                ep[(r+8)*132 + col]   = fmaxf(c[rg][ng][2] + qhs[col],     0.f);
                ep[(r+8)*132 + col+1] = fmaxf(c[rg][ng][3] + qhs[col + 1], 0.f);
            }
    } else {
        // path half: raw store to g_Cp
        #pragma unroll
        for (int rg = 0; rg < 2; rg++)
            #pragma unroll
            for (int ng = 0; ng < 8; ng++) {
                int r = wm*32 + rg*16 + gr;
                int pcol = (wn - 2)*64 + ng*8 + gc2;
                *(float2*)&g_Cp[(row0 + r)*Hh + pcol]     = make_float2(c[rg][ng][0], c[rg][ng][1]);
                *(float2*)&g_Cp[(row0 + r + 8)*Hh + pcol] = make_float2(c[rg][ng][2], c[rg][ng][3]);
            }
    }
    __syncthreads();

    // coin layer-2: 1024 outputs, 512 threads x 2
    #pragma unroll
    for (int it = 0; it < 2; it++) {
        int idx = it*512 + tid;
        int row = idx >> 3, j = idx & 7;
        float acc = b2s[j];
        #pragma unroll 8
        for (int h = 0; h < Hh; h++)
            acc = fmaf(ep[row*132 + h], w2s[h*KD + j], acc);
        g_amps[(row0 + row)*KD + j] = acc;
    }
}

// ---------------------------------------------------------------------------
// One walk step (inlines the previous step's norm reduction from g_part).
// ---------------------------------------------------------------------------
__global__ void walk_kernel(const int* __restrict__ nbrs, int step) {
    __shared__ int   nb[32*KN];
    __shared__ float red[256];
    int b  = blockIdx.y;
    int n0 = blockIdx.x * 32;
    int tid = threadIdx.x;

    const int* nb_g = nbrs + ((size_t)(b*Nn + n0))*KN;
    nb[tid]       = nb_g[tid];
    nb[tid + 256] = nb_g[tid + 256];

    float coef = 0.00390625f;   // 1/sqrt(N*K)
    if (step > 0) {
        red[tid] = g_part[b*(Nn/32) + tid];
        __syncthreads();
        for (int s = 128; s > 0; s >>= 1) {
            if (tid < s) red[tid] += red[tid + s];
            __syncthreads();
        }
        float ss = red[0];
        coef = (ss > 0.f) ? (1.0f / sqrtf(ss)) : 1.0f;
        __syncthreads();
    } else {
        __syncthreads();
    }

    int node = tid >> 3, k = tid & 7;
    int n = n0 + node;
    const float* amps_b = g_amps + (size_t)b*Nn*KD;
    const float* prev = g_ns;
    if (step > 0) prev = g_ns + (size_t)(step-1)*M_TOT*KD + (size_t)b*Nn*KD;

    float acc;
    if (step == 0) acc = amps_b[n*KD + k] * coef;
    else           acc = prev[n*KD + k] * amps_b[n*KD + k] * coef;

    #pragma unroll
    for (int j = 0; j < KN; j++) {
        int idx = nb[node*KN + j];
        if (idx >= 0 && idx < Nn) {
            float v = amps_b[idx*KD + k] * coef;
            if (step > 0) v *= prev[idx*KD + k];
            acc += v;
        }
    }
    g_ns[(size_t)step*M_TOT*KD + ((size_t)b*Nn + n)*KD + k] = acc;

    red[tid] = acc * acc;
    __syncthreads();
    for (int s = 128; s > 0; s >>= 1) {
        if (tid < s) red[tid] += red[tid + s];
        __syncthreads();
    }
    if (tid == 0) g_part[b*(Nn/32) + blockIdx.x] = red[0];
}

// ---------------------------------------------------------------------------
// Final path MLP (inlines the last norm reduction).
// ---------------------------------------------------------------------------
__global__ void final_kernel(const float* __restrict__ pw1,
                             const float* __restrict__ w2, const float* __restrict__ b2,
                             float* __restrict__ out) {
    __shared__ float wst[KD*Hh];
    __shared__ float w2s[Hh];
    __shared__ float red[256];
    int tid = threadIdx.x;
    int b = blockIdx.x >> 10;   // 1024 blocks per batch

    for (int i = tid; i < KD*Hh; i += 256) wst[i] = pw1[(size_t)Dd*Hh + i];
    if (tid < Hh) w2s[tid] = w2[tid];
    red[tid] = g_part[b*(Nn/32) + tid];
    __syncthreads();
    for (int s = 128; s > 0; s >>= 1) {
        if (tid < s) red[tid] += red[tid + s];
        __syncthreads();
    }
    float ss = red[0];
    float inv = (ss > 0.f) ? (1.0f / sqrtf(ss)) : 1.0f;

    int r = blockIdx.x*8 + (tid >> 5);
    int l = tid & 31;

    const float* nsf = g_ns + (size_t)(STEPS-1)*M_TOT*KD + (size_t)r*KD;
    float s[KD];
    #pragma unroll
    for (int k = 0; k < KD; k++) s[k] = nsf[k] * inv;

    float4 cc = *(const float4*)&g_Cp[(size_t)r*Hh + l*4];
    float4 qv = *(const float4*)&g_qh[(Bb + b)*Hh + l*4];
    float hv[4] = { cc.x+qv.x, cc.y+qv.y, cc.z+qv.z, cc.w+qv.w };
    #pragma unroll
    for (int k = 0; k < KD; k++)
        #pragma unroll
        for (int i = 0; i < 4; i++)
            hv[i] = fmaf(s[k], wst[k*Hh + l*4 + i], hv[i]);

    float part = 0.f;
    #pragma unroll
    for (int i = 0; i < 4; i++) {
        float h = fmaxf(hv[i], 0.f);
        part = fmaf(h, w2s[l*4 + i], part);
    }
    #pragma unroll
    for (int m = 16; m > 0; m >>= 1)
        part += __shfl_xor_sync(0xffffffffu, part, m);
    if (l == 0) out[r] = part + b2[0];
}

// ---------------------------------------------------------------------------
extern "C" void kernel_launch(void* const* d_in, const int* in_sizes, int n_in,
                              void* d_out, int out_size) {
    const float* sent = (const float*)d_in[0];
    const float* q    = (const float*)d_in[1];
    const int*   nbrs = (const int*)  d_in[2];
    const float* cw1  = (const float*)d_in[3];
    const float* cb1  = (const float*)d_in[4];
    const float* cw2  = (const float*)d_in[5];
    const float* cb2  = (const float*)d_in[6];
    const float* pw1  = (const float*)d_in[7];
    const float* pb1  = (const float*)d_in[8];
    const float* pw2  = (const float*)d_in[9];
    const float* pb2  = (const float*)d_in[10];
    float* out = (float*)d_out;

    cudaFuncSetAttribute(gemm_hmma, cudaFuncAttributeMaxDynamicSharedMemorySize, SM_TOTAL);

    qh_kernel<<<dim3(Bb, 2), Hh>>>(q, cw1, cb1, pw1, pb1);
    prepB_kernel<<<Dd, NB>>>(cw1, pw1);
    gemm_hmma<<<M_TOT/128, 512, SM_TOTAL>>>(sent, cw2, cb2);
    for (int s = 0; s < STEPS; s++)
        walk_kernel<<<dim3(Nn/32, Bb), 256>>>(nbrs, s);
    final_kernel<<<M_TOT/8, 256>>>(pw1, pw2, pb2, out);
}

// round 5
// speedup vs baseline: 3.0113x; 1.2665x over previous
#include <cuda_runtime.h>
#include <cuda_fp16.h>
#include <math.h>
#include <stdint.h>

#define Bb 16
#define Nn 8192
#define Dd 384
#define KN 16
#define KD 8
#define Hh 128
#define STEPS 3
#define M_TOT (Bb*Nn)   // 131072
#define NB 256          // fused output width (coin 0..127 | path 128..255)

#define APAD 24         // halves per A smem row (48B stride, odd multiple of 16B)
#define BPAD 264        // halves per B smem row (528B stride, odd multiple of 16B)

// smem buffer layout (per double-buffer slot):
//   [0, 6144)      A  (128 x 16 fp16, APAD rows)
//   [6144, 14592)  B  (16 x 256 fp16, BPAD rows)
#define SMBUF 14592
// epilogue aliases: ep[128][132] @0 (67584B), w2s @67584, qh @71680, b2 @72192
#define EP_W2 67584
#define EP_QH 71680
#define EP_B2 72192
#define SM_TOTAL 73728

// ---- scratch (alloc-free: __device__ globals, fully rewritten every launch) ----
__device__ float g_Cp[(size_t)M_TOT*Hh];      // path hidden pre-act (sent part)   64MB
__device__ float g_amps[M_TOT*KD];            // coin amplitudes                    4MB
__device__ float g_t[2][M_TOT*KD];            // walk gather arrays (ns*amps)     2x4MB
__device__ float g_nsL[M_TOT*KD];             // last step raw ns                   4MB
__device__ float g_qh[2*Bb*Hh];               // per-batch q@W + bias (coin, path)
__device__ float g_part[Bb*(Nn/32)];          // per-block sumsq partials
__device__ __half g_Bh[Dd*NB];                // fused W1, fp16, [kchunk][k16][n]

// ================= helpers =================
__device__ __forceinline__ uint32_t smem_u32(const void* p) {
    uint32_t a;
    asm("{ .reg .u64 t; cvta.to.shared.u64 t, %1; cvt.u32.u64 %0, t; }" : "=r"(a) : "l"(p));
    return a;
}
__device__ __forceinline__ void ldsm4(unsigned &r0, unsigned &r1, unsigned &r2, unsigned &r3,
                                      unsigned addr) {
    asm volatile("ldmatrix.sync.aligned.m8n8.x4.shared.b16 {%0,%1,%2,%3}, [%4];"
                 : "=r"(r0), "=r"(r1), "=r"(r2), "=r"(r3) : "r"(addr));
}
__device__ __forceinline__ void ldsm4t(unsigned &r0, unsigned &r1, unsigned &r2, unsigned &r3,
                                       unsigned addr) {
    asm volatile("ldmatrix.sync.aligned.m8n8.x4.trans.shared.b16 {%0,%1,%2,%3}, [%4];"
                 : "=r"(r0), "=r"(r1), "=r"(r2), "=r"(r3) : "r"(addr));
}
__device__ __forceinline__ void mma16816(float* c, const unsigned* a, unsigned b0, unsigned b1) {
    asm volatile(
        "mma.sync.aligned.m16n8k16.row.col.f32.f16.f16.f32 "
        "{%0,%1,%2,%3}, {%4,%5,%6,%7}, {%8,%9}, {%0,%1,%2,%3};"
        : "+f"(c[0]), "+f"(c[1]), "+f"(c[2]), "+f"(c[3])
        : "r"(a[0]), "r"(a[1]), "r"(a[2]), "r"(a[3]), "r"(b0), "r"(b1));
}
__device__ __forceinline__ uint32_t pack_h2(__half a, __half b) {
    __half2 t; t.x = a; t.y = b;
    return *(uint32_t*)&t;
}

// ---------------------------------------------------------------------------
// per-batch q contribution, parallel over k-chunks: 512 threads = 128 h x 4 kc
// ---------------------------------------------------------------------------
__global__ void qh_kernel(const float* __restrict__ q,
                          const float* __restrict__ cw1, const float* __restrict__ cb1,
                          const float* __restrict__ pw1, const float* __restrict__ pb1) {
    __shared__ float red[4][Hh];
    int b = blockIdx.x, which = blockIdx.y;
    int h = threadIdx.x & 127, kc = threadIdx.x >> 7;
    const float* w1   = which ? pw1 : cw1;
    const float* bias = which ? pb1 : cb1;
    int rowoff = which ? (Dd + KD) : Dd;
    const float* qb = q + b*Dd;
    float acc = 0.f;
    #pragma unroll 4
    for (int k = kc*96; k < kc*96 + 96; k++)
        acc = fmaf(qb[k], w1[(size_t)(rowoff + k)*Hh + h], acc);
    red[kc][h] = acc;
    __syncthreads();
    if (kc == 0)
        g_qh[(which*Bb + b)*Hh + h] = bias[h] + ((red[0][h] + red[1][h])
                                              +  (red[2][h] + red[3][h]));
}

// ---------------------------------------------------------------------------
// pre-convert fused W1 sent-block to fp16, layout [k/16][k%16][n] (n<128 coin)
// ---------------------------------------------------------------------------
__global__ void prepB_kernel(const float* __restrict__ cw1, const float* __restrict__ pw1) {
    int k = blockIdx.x;          // 0..383
    int n = threadIdx.x;         // 0..255
    const float* w = (n < Hh) ? cw1 : pw1;
    float v = w[(size_t)k*Hh + (n & (Hh-1))];
    g_Bh[(k >> 4)*(16*NB) + (k & 15)*NB + n] = __float2half_rn(v);
}

// ---------------------------------------------------------------------------
// HMMA GEMM: per CTA 128 rows x 256 cols, K=384 (24 chunks of 16), fp16 single
// pass, fp32 accum, 2-chunk-deep register prefetch + double-buffered smem.
// Fused epilogue: cols 0..127 -> coin layer-2 -> g_amps & g_t[0];
//                 cols 128..255 -> g_Cp.
// ---------------------------------------------------------------------------
__global__ void __launch_bounds__(512, 1)
gemm_hmma(const float* __restrict__ A,
          const float* __restrict__ cw2, const float* __restrict__ cb2) {
    extern __shared__ char smem[];
    const uint32_t sbase = smem_u32(smem);
    const int tid = threadIdx.x, lane = tid & 31, wid = tid >> 5;
    const int wm = wid >> 2, wn = wid & 3;
    const size_t row0 = (size_t)blockIdx.x * 128;

    float c[2][8][4];
    #pragma unroll
    for (int i = 0; i < 2; i++)
        #pragma unroll
        for (int j = 0; j < 8; j++)
            #pragma unroll
            for (int l = 0; l < 4; l++) c[i][j][l] = 0.f;

    // load assignments
    const int arow = tid >> 2, akq = (tid & 3)*4;      // A: 1 float4 / thread / chunk
    const float* Ap = A + (row0 + arow)*Dd + akq;
    const uint32_t a_sts = (uint32_t)(arow*APAD + akq)*2;
    const uint32_t b_sts = 6144u + (uint32_t)((tid >> 5)*BPAD + (tid & 31)*8)*2;

    // ldmatrix lane offsets
    const uint32_t a_lane = (uint32_t)(((lane & 15)*APAD + (lane >> 4)*8)*2);
    const uint32_t b_lane = 6144u + (uint32_t)(((((lane & 7) + ((lane >> 3) & 1)*8))*BPAD
                                        + wn*64 + (lane >> 4)*8)*2);

    float4 sA[2]; uint4 sB[2];

    #define STS_CHUNK(bufbyte, avv, bvv) do {                                  \
        char* _bc = smem + (bufbyte);                                          \
        __half _h0 = __float2half_rn((avv).x), _h1 = __float2half_rn((avv).y); \
        __half _h2 = __float2half_rn((avv).z), _h3 = __float2half_rn((avv).w); \
        *(uint2*)(_bc + a_sts) = make_uint2(pack_h2(_h0,_h1), pack_h2(_h2,_h3));\
        *(uint4*)(_bc + b_sts) = (bvv);                                        \
    } while (0)

    // preload: chunk0 -> buf0; chunks 1,2 in flight
    sA[0] = *(const float4*)Ap;
    sB[0] = *(const uint4*)(g_Bh + tid*8);
    STS_CHUNK(0, sA[0], sB[0]);
    sA[1] = *(const float4*)(Ap + 16);
    sB[1] = *(const uint4*)(g_Bh + 4096 + tid*8);
    sA[0] = *(const float4*)(Ap + 32);
    sB[0] = *(const uint4*)(g_Bh + 8192 + tid*8);
    __syncthreads();

    for (int ch = 0; ch < 24; ch++) {
        const int cur = ch & 1, nxt = cur ^ 1;
        // ---- MMA on buffer cur ----
        {
            const uint32_t sb0 = sbase + cur*SMBUF;
            unsigned bf[4][4];
            #pragma unroll
            for (int pr = 0; pr < 4; pr++)
                ldsm4t(bf[pr][0], bf[pr][1], bf[pr][2], bf[pr][3],
                       sb0 + pr*32 + b_lane);
            unsigned af[2][4];
            #pragma unroll
            for (int rg = 0; rg < 2; rg++)
                ldsm4(af[rg][0], af[rg][1], af[rg][2], af[rg][3],
                      sb0 + (uint32_t)((wm*32 + rg*16)*48) + a_lane);
            #pragma unroll
            for (int pr = 0; pr < 4; pr++)
                #pragma unroll
                for (int rg = 0; rg < 2; rg++) {
                    mma16816(c[rg][2*pr],     af[rg], bf[pr][0], bf[pr][1]);
                    mma16816(c[rg][2*pr + 1], af[rg], bf[pr][2], bf[pr][3]);
                }
        }
        if (ch < 23) STS_CHUNK(nxt*SMBUF, sA[nxt & 1], sB[nxt & 1]);
        if (ch + 3 < 24) {
            sA[nxt & 1] = *(const float4*)(Ap + (ch + 3)*16);
            sB[nxt & 1] = *(const uint4*)(g_Bh + (ch + 3)*4096 + tid*8);
        }
        __syncthreads();
    }

    // ---- epilogue ----
    const int b = blockIdx.x >> 6;             // 64 tiles per batch
    float* ep   = (float*)smem;                // [128][132]
    float* w2s  = (float*)(smem + EP_W2);
    float* qhs  = (float*)(smem + EP_QH);
    float* b2s  = (float*)(smem + EP_B2);
    for (int i = tid; i < Hh*KD; i += 512) w2s[i] = cw2[i];
    if (tid < Hh) qhs[tid] = g_qh[b*Hh + tid];
    if (tid < KD) b2s[tid] = cb2[tid];
    __syncthreads();

    const int gr = lane >> 2, gc2 = (lane & 3)*2;
    if (wn < 2) {
        // coin half: stage relu(c + qh) into ep
        #pragma unroll
        for (int rg = 0; rg < 2; rg++)
            #pragma unroll
            for (int ng = 0; ng < 8; ng++) {
                int r = wm*32 + rg*16 + gr;
                int col = wn*64 + ng*8 + gc2;
                ep[r*132 + col]       = fmaxf(c[rg][ng][0] + qhs[col],     0.f);
                ep[r*132 + col + 1]   = fmaxf(c[rg][ng][1] + qhs[col + 1], 0.f);
                ep[(r+8)*132 + col]   = fmaxf(c[rg][ng][2] + qhs[col],     0.f);
                ep[(r+8)*132 + col+1] = fmaxf(c[rg][ng][3] + qhs[col + 1], 0.f);
            }
    } else {
        // path half: raw store to g_Cp
        #pragma unroll
        for (int rg = 0; rg < 2; rg++)
            #pragma unroll
            for (int ng = 0; ng < 8; ng++) {
                int r = wm*32 + rg*16 + gr;
                int pcol = (wn - 2)*64 + ng*8 + gc2;
                *(float2*)&g_Cp[(row0 + r)*Hh + pcol]     = make_float2(c[rg][ng][0], c[rg][ng][1]);
                *(float2*)&g_Cp[(row0 + r + 8)*Hh + pcol] = make_float2(c[rg][ng][2], c[rg][ng][3]);
            }
    }
    __syncthreads();

    // coin layer-2: 1024 outputs, 512 threads x 2; also seed t0 = amps/sqrt(N*K)
    #pragma unroll
    for (int it = 0; it < 2; it++) {
        int idx = it*512 + tid;
        int row = idx >> 3, j = idx & 7;
        float acc = b2s[j];
        #pragma unroll 8
        for (int h = 0; h < Hh; h++)
            acc = fmaf(ep[row*132 + h], w2s[h*KD + j], acc);
        g_amps[(row0 + row)*KD + j]  = acc;
        g_t[0][(row0 + row)*KD + j]  = acc * 0.00390625f;
    }
}

// ---------------------------------------------------------------------------
// One walk step. Gathers t = prev_ns*amps (single array). Inlines the prev
// step's norm reduction. Steps 0,1 write t_next; step 2 writes raw ns.
// ---------------------------------------------------------------------------
__global__ void walk_kernel(const int* __restrict__ nbrs, int step) {
    __shared__ int   nb[32*KN];
    __shared__ float red[256];
    int b  = blockIdx.y;
    int n0 = blockIdx.x * 32;
    int tid = threadIdx.x;

    const int* nb_g = nbrs + ((size_t)(b*Nn + n0))*KN;
    nb[tid]       = nb_g[tid];
    nb[tid + 256] = nb_g[tid + 256];

    float coef = 1.0f;
    if (step > 0) {
        red[tid] = g_part[b*(Nn/32) + tid];
        __syncthreads();
        for (int s = 128; s > 0; s >>= 1) {
            if (tid < s) red[tid] += red[tid + s];
            __syncthreads();
        }
        float ss = red[0];
        coef = (ss > 0.f) ? rsqrtf(ss) : 1.0f;
        __syncthreads();
    } else {
        __syncthreads();
    }

    int node = tid >> 3, k = tid & 7;
    int n = n0 + node;
    const float* tb = g_t[step & 1] + (size_t)b*Nn*KD;

    float acc = tb[n*KD + k];
    #pragma unroll
    for (int j = 0; j < KN; j++) {
        int idx = nb[node*KN + j];
        if (idx >= 0 && idx < Nn) acc += tb[idx*KD + k];
    }
    float ns = coef * acc;

    size_t gi = ((size_t)b*Nn + n)*KD + k;
    if (step < STEPS - 1) g_t[(step + 1) & 1][gi] = ns * g_amps[gi];
    else                  g_nsL[gi] = ns;

    red[tid] = ns * ns;
    __syncthreads();
    for (int s = 128; s > 0; s >>= 1) {
        if (tid < s) red[tid] += red[tid + s];
        __syncthreads();
    }
    if (tid == 0) g_part[b*(Nn/32) + blockIdx.x] = red[0];
}

// ---------------------------------------------------------------------------
// Final path MLP (inlines the last norm reduction).
// ---------------------------------------------------------------------------
__global__ void final_kernel(const float* __restrict__ pw1,
                             const float* __restrict__ w2, const float* __restrict__ b2,
                             float* __restrict__ out) {
    __shared__ float wst[KD*Hh];
    __shared__ float w2s[Hh];
    __shared__ float red[256];
    int tid = threadIdx.x;
    int b = blockIdx.x >> 10;   // 1024 blocks per batch

    for (int i = tid; i < KD*Hh; i += 256) wst[i] = pw1[(size_t)Dd*Hh + i];
    if (tid < Hh) w2s[tid] = w2[tid];
    red[tid] = g_part[b*(Nn/32) + tid];
    __syncthreads();
    for (int s = 128; s > 0; s >>= 1) {
        if (tid < s) red[tid] += red[tid + s];
        __syncthreads();
    }
    float ss = red[0];
    float inv = (ss > 0.f) ? rsqrtf(ss) : 1.0f;

    int r = blockIdx.x*8 + (tid >> 5);
    int l = tid & 31;

    const float* nsf = g_nsL + (size_t)r*KD;
    float s[KD];
    #pragma unroll
    for (int k = 0; k < KD; k++) s[k] = nsf[k] * inv;

    float4 cc = *(const float4*)&g_Cp[(size_t)r*Hh + l*4];
    float4 qv = *(const float4*)&g_qh[(Bb + b)*Hh + l*4];
    float hv[4] = { cc.x+qv.x, cc.y+qv.y, cc.z+qv.z, cc.w+qv.w };
    #pragma unroll
    for (int k = 0; k < KD; k++)
        #pragma unroll
        for (int i = 0; i < 4; i++)
            hv[i] = fmaf(s[k], wst[k*Hh + l*4 + i], hv[i]);

    float part = 0.f;
    #pragma unroll
    for (int i = 0; i < 4; i++) {
        float h = fmaxf(hv[i], 0.f);
        part = fmaf(h, w2s[l*4 + i], part);
    }
    #pragma unroll
    for (int m = 16; m > 0; m >>= 1)
        part += __shfl_xor_sync(0xffffffffu, part, m);
    if (l == 0) out[r] = part + b2[0];
}

// ---------------------------------------------------------------------------
extern "C" void kernel_launch(void* const* d_in, const int* in_sizes, int n_in,
                              void* d_out, int out_size) {
    const float* sent = (const float*)d_in[0];
    const float* q    = (const float*)d_in[1];
    const int*   nbrs = (const int*)  d_in[2];
    const float* cw1  = (const float*)d_in[3];
    const float* cb1  = (const float*)d_in[4];
    const float* cw2  = (const float*)d_in[5];
    const float* cb2  = (const float*)d_in[6];
    const float* pw1  = (const float*)d_in[7];
    const float* pb1  = (const float*)d_in[8];
    const float* pw2  = (const float*)d_in[9];
    const float* pb2  = (const float*)d_in[10];
    float* out = (float*)d_out;

    cudaFuncSetAttribute(gemm_hmma, cudaFuncAttributeMaxDynamicSharedMemorySize, SM_TOTAL);

    qh_kernel<<<dim3(Bb, 2), 512>>>(q, cw1, cb1, pw1, pb1);
    prepB_kernel<<<Dd, NB>>>(cw1, pw1);
    gemm_hmma<<<M_TOT/128, 512, SM_TOTAL>>>(sent, cw2, cb2);
    for (int s = 0; s < STEPS; s++)
        walk_kernel<<<dim3(Nn/32, Bb), 256>>>(nbrs, s);
    final_kernel<<<M_TOT/8, 256>>>(pw1, pw2, pb2, out);
}